// round 1
// baseline (speedup 1.0000x reference)
#include <cuda_runtime.h>
#include <math.h>

// Problem constants (shapes fixed by the dataset)
#define KDIM 1024
#define NH   4096            // rows per matrix
#define NTOT 8192            // total rows
#define BM   128
#define BK   16
#define NTILES 64                              // NTOT / BM
#define NBLOCKS (NTILES * (NTILES + 1) / 2)    // 2080 triangular tiles

// Scratch (no allocations allowed in kernel_launch)
__device__ float  g_sq[NTOT];
__device__ float  g_colpart[KDIM];
__device__ double g_sumsq;
__device__ double g_colsq;
__device__ float  g_coef;     // -1 / (16 * bandwidth)
__device__ double g_accum;

__global__ void k_init() {
  if (threadIdx.x == 0) { g_sumsq = 0.0; g_colsq = 0.0; g_accum = 0.0; }
  for (int i = threadIdx.x; i < KDIM; i += blockDim.x) g_colpart[i] = 0.f;
}

// One warp per row: squared norms + global sum of squared norms.
__global__ void k_rowsq(const float* __restrict__ S, const float* __restrict__ T) {
  int warp = (blockIdx.x * blockDim.x + threadIdx.x) >> 5;
  int lane = threadIdx.x & 31;
  const float* row = (warp < NH) ? (S + (size_t)warp * KDIM)
                                 : (T + (size_t)(warp - NH) * KDIM);
  float s = 0.f;
  const float4* r4 = (const float4*)row;
  #pragma unroll
  for (int i = 0; i < KDIM / 4 / 32; ++i) {
    float4 v = r4[lane + i * 32];
    s += v.x * v.x + v.y * v.y + v.z * v.z + v.w * v.w;
  }
  #pragma unroll
  for (int o = 16; o; o >>= 1) s += __shfl_xor_sync(0xffffffffu, s, o);

  __shared__ double bs[8];
  int wib = threadIdx.x >> 5;
  if (lane == 0) { g_sq[warp] = s; bs[wib] = (double)s; }
  __syncthreads();
  if (threadIdx.x == 0) {
    double t = 0.0;
    #pragma unroll
    for (int i = 0; i < 8; ++i) t += bs[i];
    atomicAdd(&g_sumsq, t);
  }
}

// Partial column sums: grid (4 col-groups, 32 row-groups), 256 threads.
__global__ void k_colpart(const float* __restrict__ S, const float* __restrict__ T) {
  int c  = blockIdx.x * 256 + threadIdx.x;
  int rg = blockIdx.y;  // 0..31, each 256 rows
  const float* base = (rg < 16) ? (S + (size_t)(rg * 256) * KDIM)
                                : (T + (size_t)((rg - 16) * 256) * KDIM);
  float s = 0.f;
  #pragma unroll 8
  for (int r = 0; r < 256; ++r) s += base[(size_t)r * KDIM + c];
  atomicAdd(&g_colpart[c], s);
}

// ||colsum||^2
__global__ void k_colsq() {
  __shared__ double sh[1024];
  float v = g_colpart[threadIdx.x];
  sh[threadIdx.x] = (double)v * (double)v;
  __syncthreads();
  for (int s = 512; s; s >>= 1) {
    if (threadIdx.x < (unsigned)s) sh[threadIdx.x] += sh[threadIdx.x + s];
    __syncthreads();
  }
  if (threadIdx.x == 0) g_colsq = sh[0];
}

// bandwidth: sum(L2) = 2N*sum(sq) - 2*||colsum||^2 ; /(N^2-N) ; /4
__global__ void k_bw() {
  double sumL2 = 2.0 * (double)NTOT * g_sumsq - 2.0 * g_colsq;
  double bw = sumL2 / ((double)NTOT * (double)NTOT - (double)NTOT);
  bw *= 0.25;  // / KERNEL_MUL^(KERNEL_NUM//2) = / 2^2
  g_coef = (float)(-1.0 / (16.0 * bw));
}

// Fused Gram + multi-kernel exp + signed reduction over triangular tiles.
__global__ void __launch_bounds__(256, 2)
k_main(const float* __restrict__ S, const float* __restrict__ T) {
  __shared__ float As[BK][BM];
  __shared__ float Bs[BK][BM];

  // decode triangular block index: bid = bp*(bp+1)/2 + bq, bq <= bp
  int bid = blockIdx.x;
  int bp = (int)((sqrtf(8.0f * (float)bid + 1.0f) - 1.0f) * 0.5f);
  while ((bp + 1) * (bp + 2) / 2 <= bid) ++bp;
  while (bp * (bp + 1) / 2 > bid) --bp;
  int bq = bid - bp * (bp + 1) / 2;

  const int tid = threadIdx.x;
  const int tm = tid & 15;   // row micro-group
  const int tn = tid >> 4;   // col micro-group
  const int rowBase = bp * BM;
  const int colBase = bq * BM;

  const float* Abase = (rowBase < NH) ? (S + (size_t)rowBase * KDIM)
                                      : (T + (size_t)(rowBase - NH) * KDIM);
  const float* Bbase = (colBase < NH) ? (S + (size_t)colBase * KDIM)
                                      : (T + (size_t)(colBase - NH) * KDIM);

  float acc[8][8];
  #pragma unroll
  for (int i = 0; i < 8; ++i)
    #pragma unroll
    for (int j = 0; j < 8; ++j) acc[i][j] = 0.f;

  const int ldr0 = tid >> 2;        // 0..63
  const int ldc  = (tid & 3) * 4;   // 0,4,8,12

  for (int k0 = 0; k0 < KDIM; k0 += BK) {
    #pragma unroll
    for (int it = 0; it < 2; ++it) {
      int r = ldr0 + it * 64;
      float4 va = *(const float4*)(Abase + (size_t)r * KDIM + k0 + ldc);
      As[ldc + 0][r] = va.x; As[ldc + 1][r] = va.y;
      As[ldc + 2][r] = va.z; As[ldc + 3][r] = va.w;
      float4 vb = *(const float4*)(Bbase + (size_t)r * KDIM + k0 + ldc);
      Bs[ldc + 0][r] = vb.x; Bs[ldc + 1][r] = vb.y;
      Bs[ldc + 2][r] = vb.z; Bs[ldc + 3][r] = vb.w;
    }
    __syncthreads();
    #pragma unroll
    for (int k = 0; k < BK; ++k) {
      float a[8], b[8];
      *(float4*)&a[0] = *(const float4*)&As[k][tm * 8];
      *(float4*)&a[4] = *(const float4*)&As[k][tm * 8 + 4];
      *(float4*)&b[0] = *(const float4*)&Bs[k][tn * 8];
      *(float4*)&b[4] = *(const float4*)&Bs[k][tn * 8 + 4];
      #pragma unroll
      for (int i = 0; i < 8; ++i)
        #pragma unroll
        for (int j = 0; j < 8; ++j)
          acc[i][j] = fmaf(a[i], b[j], acc[i][j]);
    }
    __syncthreads();
  }

  // Fused epilogue: L2 -> v=exp(-L2/(16b)) -> v+v^2+v^4+v^8+v^16
  const float coef = g_coef;
  const int p0 = rowBase + tm * 8;
  const int q0 = colBase + tn * 8;
  float sqp[8], sqq[8];
  #pragma unroll
  for (int i = 0; i < 8; ++i) { sqp[i] = g_sq[p0 + i]; sqq[i] = g_sq[q0 + i]; }

  float fsum = 0.f;
  #pragma unroll
  for (int i = 0; i < 8; ++i) {
    #pragma unroll
    for (int j = 0; j < 8; ++j) {
      float L2 = sqp[i] + sqq[j] - 2.0f * acc[i][j];
      float v  = __expf(L2 * coef);
      float v2 = v * v, v4 = v2 * v2, v8 = v4 * v4, v16 = v8 * v8;
      fsum += (v + v2 + v4 + v8 + v16);
    }
  }
  // sign: same-side quadrants +1, cross -1 (uniform per tile; NH % BM == 0)
  float sgn = ((bp < NTILES / 2) == (bq < NTILES / 2)) ? 1.f : -1.f;
  float wgt = (bp == bq) ? 1.f : 2.f;  // symmetry: off-diagonal tiles counted twice

  __shared__ double red[256];
  red[tid] = (double)(sgn * wgt) * (double)fsum;
  __syncthreads();
  for (int s = 128; s; s >>= 1) {
    if (tid < s) red[tid] += red[tid + s];
    __syncthreads();
  }
  if (tid == 0) atomicAdd(&g_accum, red[0]);
}

__global__ void k_final(float* out) {
  out[0] = (float)(g_accum / ((double)NH * (double)NH));
}

extern "C" void kernel_launch(void* const* d_in, const int* in_sizes, int n_in,
                              void* d_out, int out_size) {
  (void)in_sizes; (void)n_in; (void)out_size;
  const float* S = (const float*)d_in[0];
  const float* T = (const float*)d_in[1];

  k_init<<<1, 256>>>();
  k_rowsq<<<NTOT / 8, 256>>>(S, T);           // 8 warps/block -> 1024 blocks
  k_colpart<<<dim3(4, 32), 256>>>(S, T);
  k_colsq<<<1, 1024>>>();
  k_bw<<<1, 1>>>();
  k_main<<<NBLOCKS, 256>>>(S, T);
  k_final<<<1, 1>>>((float*)d_out);
}

// round 3
// speedup vs baseline: 7.7324x; 7.7324x over previous
#include <cuda_runtime.h>
#include <cuda_bf16.h>
#include <math.h>
#include <stdint.h>

#define KDIM 1024
#define NH   4096
#define NTOT 8192
#define BM   128
#define NTILES (NTOT / BM)                       // 64
#define NBLOCKS (NTILES * (NTILES + 1) / 2)      // 2080
#define CHUNK 64                                 // K elements per stage (128 bytes)
#define NCHUNK (KDIM / CHUNK)                    // 16
#define TILE_BYTES (BM * 128)                    // 16 KB per operand per stage
#define STAGE_BYTES (2 * TILE_BYTES)             // 32 KB
#define DYN_BYTES (2 * STAGE_BYTES + 256)        // 2 stages + alignment slack

// ---------------- device scratch ----------------
__device__ float  g_sq[NTOT];
__device__ float  g_colpart[KDIM];
__device__ double g_sumsq;
__device__ double g_colsq;
__device__ float  g_coef;     // -1 / (16 * bandwidth)
__device__ double g_accum;
__device__ __nv_bfloat16 g_total[(size_t)NTOT * KDIM];   // bf16 copy of [S;T]

// ---------------- PTX helpers (all plain sm_80+ PTX, no 'a' features) ----------------
__device__ __forceinline__ uint32_t smem_u32(const void* p) {
  uint32_t a;
  asm("{ .reg .u64 t; cvta.to.shared.u64 t, %1; cvt.u32.u64 %0, t; }" : "=r"(a) : "l"(p));
  return a;
}
__device__ __forceinline__ void cp16(uint32_t dst, const void* src) {
  asm volatile("cp.async.cg.shared.global [%0], [%1], 16;" :: "r"(dst), "l"(src) : "memory");
}
__device__ __forceinline__ void cp_commit() {
  asm volatile("cp.async.commit_group;" ::: "memory");
}
template <int N>
__device__ __forceinline__ void cp_wait() {
  asm volatile("cp.async.wait_group %0;" :: "n"(N) : "memory");
}
__device__ __forceinline__ void ldsm4(uint32_t* r, uint32_t addr) {
  asm volatile("ldmatrix.sync.aligned.m8n8.x4.shared.b16 {%0,%1,%2,%3}, [%4];"
               : "=r"(r[0]), "=r"(r[1]), "=r"(r[2]), "=r"(r[3]) : "r"(addr));
}
__device__ __forceinline__ void mma16816(float* c, const uint32_t* a, uint32_t b0, uint32_t b1) {
  asm volatile(
    "mma.sync.aligned.m16n8k16.row.col.f32.bf16.bf16.f32 "
    "{%0,%1,%2,%3}, {%4,%5,%6,%7}, {%8,%9}, {%0,%1,%2,%3};"
    : "+f"(c[0]), "+f"(c[1]), "+f"(c[2]), "+f"(c[3])
    : "r"(a[0]), "r"(a[1]), "r"(a[2]), "r"(a[3]), "r"(b0), "r"(b1));
}

// ---------------- small kernels ----------------
__global__ void k_init() {
  if (threadIdx.x == 0) { g_sumsq = 0.0; g_colsq = 0.0; g_accum = 0.0; }
  for (int i = threadIdx.x; i < KDIM; i += blockDim.x) g_colpart[i] = 0.f;
}

__global__ void k_convert(const float* __restrict__ S, const float* __restrict__ T) {
  size_t i = (size_t)blockIdx.x * blockDim.x + threadIdx.x;   // over 2,097,152 float4s
  const size_t HALF = (size_t)NH * KDIM / 4;
  float4 v = (i < HALF) ? ((const float4*)S)[i] : ((const float4*)T)[i - HALF];
  __nv_bfloat162 lo = __floats2bfloat162_rn(v.x, v.y);
  __nv_bfloat162 hi = __floats2bfloat162_rn(v.z, v.w);
  uint2 pk;
  pk.x = *(uint32_t*)&lo;
  pk.y = *(uint32_t*)&hi;
  *(uint2*)(g_total + i * 4) = pk;
}

__global__ void k_rowsq(const float* __restrict__ S, const float* __restrict__ T) {
  int warp = (blockIdx.x * blockDim.x + threadIdx.x) >> 5;
  int lane = threadIdx.x & 31;
  const float* row = (warp < NH) ? (S + (size_t)warp * KDIM)
                                 : (T + (size_t)(warp - NH) * KDIM);
  float s = 0.f;
  const float4* r4 = (const float4*)row;
  #pragma unroll
  for (int i = 0; i < KDIM / 4 / 32; ++i) {
    float4 v = r4[lane + i * 32];
    s += v.x * v.x + v.y * v.y + v.z * v.z + v.w * v.w;
  }
  #pragma unroll
  for (int o = 16; o; o >>= 1) s += __shfl_xor_sync(0xffffffffu, s, o);

  __shared__ double bs[8];
  int wib = threadIdx.x >> 5;
  if (lane == 0) { g_sq[warp] = s; bs[wib] = (double)s; }
  __syncthreads();
  if (threadIdx.x == 0) {
    double t = 0.0;
    #pragma unroll
    for (int i = 0; i < 8; ++i) t += bs[i];
    atomicAdd(&g_sumsq, t);
  }
}

__global__ void k_colpart(const float* __restrict__ S, const float* __restrict__ T) {
  int c  = blockIdx.x * 256 + threadIdx.x;
  int rg = blockIdx.y;
  const float* base = (rg < 16) ? (S + (size_t)(rg * 256) * KDIM)
                                : (T + (size_t)((rg - 16) * 256) * KDIM);
  float s = 0.f;
  #pragma unroll 8
  for (int r = 0; r < 256; ++r) s += base[(size_t)r * KDIM + c];
  atomicAdd(&g_colpart[c], s);
}

__global__ void k_colsq() {
  __shared__ double sh[1024];
  float v = g_colpart[threadIdx.x];
  sh[threadIdx.x] = (double)v * (double)v;
  __syncthreads();
  for (int s = 512; s; s >>= 1) {
    if (threadIdx.x < (unsigned)s) sh[threadIdx.x] += sh[threadIdx.x + s];
    __syncthreads();
  }
  if (threadIdx.x == 0) g_colsq = sh[0];
}

__global__ void k_bw() {
  double sumL2 = 2.0 * (double)NTOT * g_sumsq - 2.0 * g_colsq;
  double bw = sumL2 / ((double)NTOT * (double)NTOT - (double)NTOT);
  bw *= 0.25;
  g_coef = (float)(-1.0 / (16.0 * bw));
}

// ---------------- Gram tile via mma.sync + fused MMD epilogue ----------------
// SW128 swizzle on 128-byte rows: 16B-chunk index (bits [6:4]) XOR (row & 7).
__device__ __forceinline__ void load_stage(uint32_t sA, const __nv_bfloat16* Ab,
                                           const __nv_bfloat16* Bb, int t, int tid) {
  #pragma unroll
  for (int i = 0; i < 4; ++i) {
    int g   = tid + i * 256;
    int row = g >> 3;
    int cc  = g & 7;
    uint32_t soff = (uint32_t)row * 128u + (uint32_t)((cc ^ (row & 7)) << 4);
    const char* ga = (const char*)(Ab + (size_t)row * KDIM + t * CHUNK) + cc * 16;
    const char* gb = (const char*)(Bb + (size_t)row * KDIM + t * CHUNK) + cc * 16;
    cp16(sA + soff, ga);
    cp16(sA + TILE_BYTES + soff, gb);
  }
  cp_commit();
}

__global__ void __launch_bounds__(256, 2)
k_gemm() {
  extern __shared__ char dsm[];
  __shared__ double s_red[8];

  const int tid  = threadIdx.x;
  const int wid  = tid >> 5;
  const int lane = tid & 31;

  // triangular tile decode: bid = bp*(bp+1)/2 + bq
  int bid = blockIdx.x;
  int bp = (int)((sqrtf(8.0f * (float)bid + 1.0f) - 1.0f) * 0.5f);
  while ((bp + 1) * (bp + 2) / 2 <= bid) ++bp;
  while (bp * (bp + 1) / 2 > bid) --bp;
  int bq = bid - bp * (bp + 1) / 2;
  const int rowBase = bp * BM;
  const int colBase = bq * BM;

  const __nv_bfloat16* Ab = g_total + (size_t)rowBase * KDIM;
  const __nv_bfloat16* Bb = g_total + (size_t)colBase * KDIM;

  uint32_t sm0 = (smem_u32(dsm) + 127u) & ~127u;  // stage 0; stage1 at +STAGE_BYTES

  const int warp_m = wid & 1;    // 0..1 -> 64-row half
  const int warp_n = wid >> 1;   // 0..3 -> 32-col quarter
  const int lr  = lane & 7;
  const int sub = lane >> 3;     // ldmatrix sub-matrix id

  // A fragment source rows/chunk-xor (per m-tile)
  uint32_t a_rowoff[4], a_rswz[4];
  #pragma unroll
  for (int mt = 0; mt < 4; ++mt) {
    int row = warp_m * 64 + mt * 16 + (sub & 1) * 8 + lr;
    a_rowoff[mt] = (uint32_t)row * 128u;
    a_rswz[mt]   = (uint32_t)(row & 7);
  }
  const uint32_t a_kbit = (uint32_t)(sub >> 1);   // +16B for k8..15 matrices

  // B fragment source rows (per n-tile-pair)
  uint32_t b_rowoff[2], b_rswz[2];
  #pragma unroll
  for (int np = 0; np < 2; ++np) {
    int row = warp_n * 32 + np * 16 + (sub >> 1) * 8 + lr;
    b_rowoff[np] = (uint32_t)row * 128u;
    b_rswz[np]   = (uint32_t)(row & 7);
  }
  const uint32_t b_kbit = (uint32_t)(sub & 1);

  float acc[4][4][4];
  #pragma unroll
  for (int i = 0; i < 4; ++i)
    #pragma unroll
    for (int j = 0; j < 4; ++j)
      #pragma unroll
      for (int r = 0; r < 4; ++r) acc[i][j][r] = 0.f;

  load_stage(sm0, Ab, Bb, 0, tid);
  load_stage(sm0 + STAGE_BYTES, Ab, Bb, 1, tid);

  for (int t = 0; t < NCHUNK; ++t) {
    if (t == NCHUNK - 1) cp_wait<0>(); else cp_wait<1>();
    __syncthreads();

    uint32_t sA = sm0 + (t & 1) * STAGE_BYTES;
    uint32_t sB = sA + TILE_BYTES;

    #pragma unroll
    for (int kk = 0; kk < 4; ++kk) {
      uint32_t kk2 = (uint32_t)(kk * 2);
      uint32_t af[4][4];
      #pragma unroll
      for (int mt = 0; mt < 4; ++mt)
        ldsm4(af[mt], sA + a_rowoff[mt] + (((kk2 + a_kbit) ^ a_rswz[mt]) << 4));
      uint32_t bf[2][4];
      #pragma unroll
      for (int np = 0; np < 2; ++np)
        ldsm4(bf[np], sB + b_rowoff[np] + (((kk2 + b_kbit) ^ b_rswz[np]) << 4));
      #pragma unroll
      for (int mt = 0; mt < 4; ++mt) {
        #pragma unroll
        for (int nt = 0; nt < 4; ++nt)
          mma16816(acc[mt][nt], af[mt], bf[nt >> 1][(nt & 1) * 2],
                   bf[nt >> 1][(nt & 1) * 2 + 1]);
      }
    }

    __syncthreads();
    if (t + 2 < NCHUNK) load_stage(sm0 + (t & 1) * STAGE_BYTES, Ab, Bb, t + 2, tid);
  }

  // ---- fused epilogue ----
  const float coef = g_coef;
  const int tg = lane >> 2;   // row within 16-tile (0..7)
  const int tc = lane & 3;    // col pair (0..3)

  float sqp[4][2], sqq[4][2];
  #pragma unroll
  for (int mt = 0; mt < 4; ++mt) {
    int p0 = rowBase + warp_m * 64 + mt * 16 + tg;
    sqp[mt][0] = g_sq[p0];
    sqp[mt][1] = g_sq[p0 + 8];
  }
  #pragma unroll
  for (int nt = 0; nt < 4; ++nt) {
    int q0 = colBase + warp_n * 32 + nt * 8 + tc * 2;
    sqq[nt][0] = g_sq[q0];
    sqq[nt][1] = g_sq[q0 + 1];
  }

  float fsum = 0.f;
  #pragma unroll
  for (int mt = 0; mt < 4; ++mt) {
    #pragma unroll
    for (int nt = 0; nt < 4; ++nt) {
      #pragma unroll
      for (int r = 0; r < 4; ++r) {
        float L2 = sqp[mt][r >> 1] + sqq[nt][r & 1] - 2.0f * acc[mt][nt][r];
        float v  = __expf(L2 * coef);
        float v2 = v * v, v4 = v2 * v2, v8 = v4 * v4;
        fsum += v + v2 + v4 + v8 + v8 * v8;
      }
    }
  }
  double d = (double)fsum;
  #pragma unroll
  for (int o = 16; o; o >>= 1) d += __shfl_xor_sync(0xffffffffu, d, o);
  if (lane == 0) s_red[wid] = d;
  __syncthreads();
  if (tid == 0) {
    double t = 0.0;
    #pragma unroll
    for (int i = 0; i < 8; ++i) t += s_red[i];
    double sgn = ((bp < NTILES / 2) == (bq < NTILES / 2)) ? 1.0 : -1.0;
    if (bp != bq) sgn *= 2.0;
    atomicAdd(&g_accum, sgn * t);
  }
}

__global__ void k_final(float* out) {
  out[0] = (float)(g_accum / ((double)NH * (double)NH));
}

// ---------------- host launch ----------------
extern "C" void kernel_launch(void* const* d_in, const int* in_sizes, int n_in,
                              void* d_out, int out_size) {
  (void)in_sizes; (void)n_in; (void)out_size;
  const float* S = (const float*)d_in[0];
  const float* T = (const float*)d_in[1];

  cudaFuncSetAttribute(k_gemm, cudaFuncAttributeMaxDynamicSharedMemorySize, DYN_BYTES);

  k_init<<<1, 256>>>();
  k_convert<<<(NTOT * (KDIM / 4)) / 256, 256>>>(S, T);
  k_rowsq<<<NTOT / 8, 256>>>(S, T);
  k_colpart<<<dim3(4, 32), 256>>>(S, T);
  k_colsq<<<1, 1024>>>();
  k_bw<<<1, 1>>>();
  k_gemm<<<NBLOCKS, 256, DYN_BYTES>>>();
  k_final<<<1, 1>>>((float*)d_out);
}

// round 5
// speedup vs baseline: 7.8096x; 1.0100x over previous
#include <cuda_runtime.h>
#include <cuda_bf16.h>
#include <math.h>
#include <stdint.h>

#define KDIM 1024
#define NH   4096
#define NTOT 8192
#define BM   128
#define NTILES (NTOT / BM)                       // 64
#define NBLOCKS (NTILES * (NTILES + 1) / 2)      // 2080
#define CHUNK 64                                 // K elements per stage (128 bytes)
#define NCHUNK (KDIM / CHUNK)                    // 16
#define NST 3                                    // cp.async pipeline stages
#define TILE_BYTES (BM * 128)                    // 16 KB per operand per stage
#define STAGE_BYTES (2 * TILE_BYTES)             // 32 KB
#define DYN_BYTES (NST * STAGE_BYTES + 256)

#define PRE_BLOCKS 256                           // k_pre grid

// ---------------- device scratch ----------------
__device__ float  g_sq[NTOT];
__device__ float  g_colpart_blk[PRE_BLOCKS][KDIM];  // per-block column sums (1 MB)
__device__ double g_sumsq_blk[PRE_BLOCKS];
__device__ float  g_coef;     // -1 / (16 * bandwidth)
__device__ double g_accum;
__device__ __nv_bfloat16 g_total[(size_t)NTOT * KDIM];   // bf16 copy of [S;T]

// ---------------- PTX helpers (plain sm_80+ PTX, no 'a' features) ----------------
__device__ __forceinline__ uint32_t smem_u32(const void* p) {
  uint32_t a;
  asm("{ .reg .u64 t; cvta.to.shared.u64 t, %1; cvt.u32.u64 %0, t; }" : "=r"(a) : "l"(p));
  return a;
}
__device__ __forceinline__ void cp16(uint32_t dst, const void* src) {
  asm volatile("cp.async.cg.shared.global [%0], [%1], 16;" :: "r"(dst), "l"(src) : "memory");
}
__device__ __forceinline__ void cp_commit() {
  asm volatile("cp.async.commit_group;" ::: "memory");
}
template <int N>
__device__ __forceinline__ void cp_wait() {
  asm volatile("cp.async.wait_group %0;" :: "n"(N) : "memory");
}
__device__ __forceinline__ void ldsm4(uint32_t* r, uint32_t addr) {
  asm volatile("ldmatrix.sync.aligned.m8n8.x4.shared.b16 {%0,%1,%2,%3}, [%4];"
               : "=r"(r[0]), "=r"(r[1]), "=r"(r[2]), "=r"(r[3]) : "r"(addr));
}
__device__ __forceinline__ void mma16816(float* c, const uint32_t* a, uint32_t b0, uint32_t b1) {
  asm volatile(
    "mma.sync.aligned.m16n8k16.row.col.f32.bf16.bf16.f32 "
    "{%0,%1,%2,%3}, {%4,%5,%6,%7}, {%8,%9}, {%0,%1,%2,%3};"
    : "+f"(c[0]), "+f"(c[1]), "+f"(c[2]), "+f"(c[3])
    : "r"(a[0]), "r"(a[1]), "r"(a[2]), "r"(a[3]), "r"(b0), "r"(b1));
}

// ---------------- fused preprocessing ----------------
// grid: 256 blocks x 256 threads (8 warps); each warp handles 4 rows.
// Per row: read fp32, convert+store bf16, row sq-norm; accumulate column sums.
__global__ void __launch_bounds__(256)
k_pre(const float* __restrict__ S, const float* __restrict__ T) {
  __shared__ float  scol[KDIM];
  __shared__ double ssq[8];

  const int tid  = threadIdx.x;
  const int wid  = tid >> 5;
  const int lane = tid & 31;

  if (blockIdx.x == 0 && tid == 0) g_accum = 0.0;

  #pragma unroll
  for (int i = 0; i < KDIM / 256; ++i) scol[tid + i * 256] = 0.f;
  __syncthreads();

  float4 colacc[8];
  #pragma unroll
  for (int i = 0; i < 8; ++i) colacc[i] = make_float4(0.f, 0.f, 0.f, 0.f);

  double wsumsq = 0.0;   // lane 0's accumulator (post-shuffle sq is full row norm)

  #pragma unroll
  for (int r = 0; r < 4; ++r) {
    int row = blockIdx.x * 32 + wid * 4 + r;
    const float4* src = (const float4*)((row < NH) ? (S + (size_t)row * KDIM)
                                                   : (T + (size_t)(row - NH) * KDIM));
    float sq = 0.f;
    #pragma unroll
    for (int i = 0; i < 8; ++i) {
      float4 v = src[i * 32 + lane];
      sq += v.x * v.x + v.y * v.y + v.z * v.z + v.w * v.w;
      colacc[i].x += v.x; colacc[i].y += v.y;
      colacc[i].z += v.z; colacc[i].w += v.w;
      __nv_bfloat162 lo = __floats2bfloat162_rn(v.x, v.y);
      __nv_bfloat162 hi = __floats2bfloat162_rn(v.z, v.w);
      uint2 pk;
      pk.x = *(uint32_t*)&lo;
      pk.y = *(uint32_t*)&hi;
      *(uint2*)(g_total + (size_t)row * KDIM + i * 128 + lane * 4) = pk;
    }
    #pragma unroll
    for (int o = 16; o; o >>= 1) sq += __shfl_xor_sync(0xffffffffu, sq, o);
    if (lane == 0) g_sq[row] = sq;
    wsumsq += (double)sq;   // counted once per warp via lane 0's ssq write below
  }

  // column partial sums -> smem (atomic across warps; lanes hit distinct banks)
  #pragma unroll
  for (int i = 0; i < 8; ++i) {
    int c = i * 128 + lane * 4;
    atomicAdd(&scol[c + 0], colacc[i].x);
    atomicAdd(&scol[c + 1], colacc[i].y);
    atomicAdd(&scol[c + 2], colacc[i].z);
    atomicAdd(&scol[c + 3], colacc[i].w);
  }
  if (lane == 0) ssq[wid] = wsumsq;
  __syncthreads();

  #pragma unroll
  for (int i = 0; i < KDIM / 256; ++i) {
    int c = tid + i * 256;
    g_colpart_blk[blockIdx.x][c] = scol[c];
  }
  if (tid == 0) {
    double t = 0.0;
    #pragma unroll
    for (int i = 0; i < 8; ++i) t += ssq[i];
    g_sumsq_blk[blockIdx.x] = t;
  }
}

// reduce colsums + sumsq, compute coefficient
__global__ void k_bw2() {
  __shared__ double sh[1024];
  const int tid = threadIdx.x;

  float colsum = 0.f;
  for (int b = 0; b < PRE_BLOCKS; ++b) colsum += g_colpart_blk[b][tid];
  sh[tid] = (double)colsum * (double)colsum;
  __syncthreads();
  for (int s = 512; s; s >>= 1) {
    if (tid < s) sh[tid] += sh[tid + s];
    __syncthreads();
  }
  double colsq = sh[0];
  __syncthreads();

  sh[tid] = (tid < PRE_BLOCKS) ? g_sumsq_blk[tid] : 0.0;
  __syncthreads();
  for (int s = 512; s; s >>= 1) {
    if (tid < s) sh[tid] += sh[tid + s];
    __syncthreads();
  }
  if (tid == 0) {
    double sumsq = sh[0];
    double sumL2 = 2.0 * (double)NTOT * sumsq - 2.0 * colsq;
    double bw = sumL2 / ((double)NTOT * (double)NTOT - (double)NTOT);
    bw *= 0.25;
    g_coef = (float)(-1.0 / (16.0 * bw));
  }
}

// ---------------- Gram tile via mma.sync + fused MMD epilogue ----------------
// SW128 swizzle on 128-byte rows: 16B-chunk index (bits [6:4]) XOR (row & 7).
__device__ __forceinline__ void load_stage(uint32_t sA, const __nv_bfloat16* Ab,
                                           const __nv_bfloat16* Bb, int t, int tid) {
  #pragma unroll
  for (int i = 0; i < 4; ++i) {
    int g   = tid + i * 256;
    int row = g >> 3;
    int cc  = g & 7;
    uint32_t soff = (uint32_t)row * 128u + (uint32_t)((cc ^ (row & 7)) << 4);
    const char* ga = (const char*)(Ab + (size_t)row * KDIM + t * CHUNK) + cc * 16;
    const char* gb = (const char*)(Bb + (size_t)row * KDIM + t * CHUNK) + cc * 16;
    cp16(sA + soff, ga);
    cp16(sA + TILE_BYTES + soff, gb);
  }
  cp_commit();
}

__global__ void __launch_bounds__(256, 2)
k_gemm() {
  extern __shared__ char dsm[];
  __shared__ double s_red[8];

  const int tid  = threadIdx.x;
  const int wid  = tid >> 5;
  const int lane = tid & 31;

  // triangular tile decode: bid = bp*(bp+1)/2 + bq
  int bid = blockIdx.x;
  int bp = (int)((sqrtf(8.0f * (float)bid + 1.0f) - 1.0f) * 0.5f);
  while ((bp + 1) * (bp + 2) / 2 <= bid) ++bp;
  while (bp * (bp + 1) / 2 > bid) --bp;
  int bq = bid - bp * (bp + 1) / 2;
  const int rowBase = bp * BM;
  const int colBase = bq * BM;

  const __nv_bfloat16* Ab = g_total + (size_t)rowBase * KDIM;
  const __nv_bfloat16* Bb = g_total + (size_t)colBase * KDIM;

  uint32_t sm0 = (smem_u32(dsm) + 127u) & ~127u;

  const int warp_m = wid & 1;    // 0..1 -> 64-row half
  const int warp_n = wid >> 1;   // 0..3 -> 32-col quarter
  const int lr  = lane & 7;
  const int sub = lane >> 3;

  uint32_t a_rowoff[4], a_rswz[4];
  #pragma unroll
  for (int mt = 0; mt < 4; ++mt) {
    int row = warp_m * 64 + mt * 16 + (sub & 1) * 8 + lr;
    a_rowoff[mt] = (uint32_t)row * 128u;
    a_rswz[mt]   = (uint32_t)(row & 7);
  }
  const uint32_t a_kbit = (uint32_t)(sub >> 1);

  uint32_t b_rowoff[2], b_rswz[2];
  #pragma unroll
  for (int np = 0; np < 2; ++np) {
    int row = warp_n * 32 + np * 16 + (sub >> 1) * 8 + lr;
    b_rowoff[np] = (uint32_t)row * 128u;
    b_rswz[np]   = (uint32_t)(row & 7);
  }
  const uint32_t b_kbit = (uint32_t)(sub & 1);

  float acc[4][4][4];
  #pragma unroll
  for (int i = 0; i < 4; ++i)
    #pragma unroll
    for (int j = 0; j < 4; ++j)
      #pragma unroll
      for (int r = 0; r < 4; ++r) acc[i][j][r] = 0.f;

  load_stage(sm0 + 0 * STAGE_BYTES, Ab, Bb, 0, tid);
  load_stage(sm0 + 1 * STAGE_BYTES, Ab, Bb, 1, tid);
  load_stage(sm0 + 2 * STAGE_BYTES, Ab, Bb, 2, tid);

  int st = 0;
  for (int t = 0; t < NCHUNK; ++t) {
    cp_wait<2>();
    __syncthreads();

    uint32_t sA = sm0 + st * STAGE_BYTES;
    uint32_t sB = sA + TILE_BYTES;

    #pragma unroll
    for (int kk = 0; kk < 4; ++kk) {
      uint32_t kk2 = (uint32_t)(kk * 2);
      uint32_t af[4][4];
      #pragma unroll
      for (int mt = 0; mt < 4; ++mt)
        ldsm4(af[mt], sA + a_rowoff[mt] + (((kk2 + a_kbit) ^ a_rswz[mt]) << 4));
      uint32_t bf[2][4];
      #pragma unroll
      for (int np = 0; np < 2; ++np)
        ldsm4(bf[np], sB + b_rowoff[np] + (((kk2 + b_kbit) ^ b_rswz[np]) << 4));
      #pragma unroll
      for (int mt = 0; mt < 4; ++mt) {
        #pragma unroll
        for (int nt = 0; nt < 4; ++nt)
          mma16816(acc[mt][nt], af[mt], bf[nt >> 1][(nt & 1) * 2],
                   bf[nt >> 1][(nt & 1) * 2 + 1]);
      }
    }

    __syncthreads();
    if (t + NST < NCHUNK) load_stage(sm0 + st * STAGE_BYTES, Ab, Bb, t + NST, tid);
    st = (st == NST - 1) ? 0 : st + 1;
  }

  // ---- fused epilogue ----
  const float coef = g_coef;
  const int tg = lane >> 2;
  const int tc = lane & 3;

  float sqp[4][2], sqq[4][2];
  #pragma unroll
  for (int mt = 0; mt < 4; ++mt) {
    int p0 = rowBase + warp_m * 64 + mt * 16 + tg;
    sqp[mt][0] = g_sq[p0];
    sqp[mt][1] = g_sq[p0 + 8];
  }
  #pragma unroll
  for (int nt = 0; nt < 4; ++nt) {
    int q0 = colBase + warp_n * 32 + nt * 8 + tc * 2;
    sqq[nt][0] = g_sq[q0];
    sqq[nt][1] = g_sq[q0 + 1];
  }

  float fsum = 0.f;
  #pragma unroll
  for (int mt = 0; mt < 4; ++mt) {
    #pragma unroll
    for (int nt = 0; nt < 4; ++nt) {
      #pragma unroll
      for (int r = 0; r < 4; ++r) {
        float L2 = sqp[mt][r >> 1] + sqq[nt][r & 1] - 2.0f * acc[mt][nt][r];
        float v  = __expf(L2 * coef);
        float v2 = v * v, v4 = v2 * v2, v8 = v4 * v4;
        fsum += v + v2 + v4 + v8 + v8 * v8;
      }
    }
  }
  double d = (double)fsum;
  #pragma unroll
  for (int o = 16; o; o >>= 1) d += __shfl_xor_sync(0xffffffffu, d, o);
  if (lane == 0) s_red[wid] = d;
  __syncthreads();
  if (tid == 0) {
    double t = 0.0;
    #pragma unroll
    for (int i = 0; i < 8; ++i) t += s_red[i];
    double sgn = ((bp < NTILES / 2) == (bq < NTILES / 2)) ? 1.0 : -1.0;
    if (bp != bq) sgn *= 2.0;
    atomicAdd(&g_accum, sgn * t);
  }
}

__global__ void k_final(float* out) {
  out[0] = (float)(g_accum / ((double)NH * (double)NH));
}

// ---------------- host launch ----------------
extern "C" void kernel_launch(void* const* d_in, const int* in_sizes, int n_in,
                              void* d_out, int out_size) {
  (void)in_sizes; (void)n_in; (void)out_size;
  const float* S = (const float*)d_in[0];
  const float* T = (const float*)d_in[1];

  cudaFuncSetAttribute(k_gemm, cudaFuncAttributeMaxDynamicSharedMemorySize, DYN_BYTES);

  k_pre<<<PRE_BLOCKS, 256>>>(S, T);
  k_bw2<<<1, 1024>>>();
  k_gemm<<<NBLOCKS, 256, DYN_BYTES>>>();
  k_final<<<1, 1>>>((float*)d_out);
}